// round 11
// baseline (speedup 1.0000x reference)
#include <cuda_runtime.h>
#include <cuda_bf16.h>
#include <math.h>
#include <stdint.h>

// ---------------- problem constants ----------------
#define MAXB     1024
#define DIM      128
#define NCHUNKS  18
#define NSLOTS   (NCHUNKS * 4)     // per-chunk key-quarters
#define PK       4                 // stored candidate depth per slot
#define K8       8                 // merge list depth
#define TOPK     5
#define RESC     10                // rescored candidates per query
#define INV_T    10.0f
#define NPADMAX  (1564 * 128)

// ---------------- device scratch ----------------
__device__ int   g_excl[MAXB];
__device__ float g_qn[MAXB * DIM];                       // normalized queries fp32
__device__ float g_pval[8 * NSLOTS * 128 * PK];
__device__ int   g_pidx[8 * NSLOTS * 128 * PK];
__device__ __nv_bfloat16 g_qh[MAXB * DIM];
__device__ __nv_bfloat16 g_kh[(size_t)NPADMAX * DIM];    // 51.2 MB

// ---------------- PTX helpers ----------------
__device__ __forceinline__ uint32_t smem_u32(const void* p) {
    uint32_t a;
    asm("{ .reg .u64 t; cvta.to.shared.u64 t, %1; cvt.u32.u64 %0, t; }" : "=r"(a) : "l"(p));
    return a;
}
__device__ __forceinline__ void cp16(uint32_t s, const void* g) {
    asm volatile("cp.async.cg.shared.global [%0], [%1], 16;" :: "r"(s), "l"(g));
}
#define CP_COMMIT()  asm volatile("cp.async.commit_group;")
#define CP_WAIT(n)   asm volatile("cp.async.wait_group %0;" :: "n"(n))

#define LDSM4(r0, r1, r2, r3, addr)                                         \
    asm volatile("ldmatrix.sync.aligned.m8n8.x4.shared.b16 {%0,%1,%2,%3}, [%4];" \
                 : "=r"(r0), "=r"(r1), "=r"(r2), "=r"(r3) : "r"(addr))

#define MMA16816(c, a, b0, b1)                                              \
    asm volatile("mma.sync.aligned.m16n8k16.row.col.f32.bf16.bf16.f32 "     \
                 "{%0,%1,%2,%3},{%4,%5,%6,%7},{%8,%9},{%0,%1,%2,%3};"       \
                 : "+f"((c)[0]), "+f"((c)[1]), "+f"((c)[2]), "+f"((c)[3])   \
                 : "r"((a)[0]), "r"((a)[1]), "r"((a)[2]), "r"((a)[3]),      \
                   "r"(b0), "r"(b1))

// first-k MMA: D = A*B + 0 (separate zero C input; kills acc-init MOVs)
#define MMA16816_Z(c, a, b0, b1, zr)                                        \
    asm volatile("mma.sync.aligned.m16n8k16.row.col.f32.bf16.bf16.f32 "     \
                 "{%0,%1,%2,%3},{%4,%5,%6,%7},{%8,%9},{%10,%10,%10,%10};"   \
                 : "=f"((c)[0]), "=f"((c)[1]), "=f"((c)[2]), "=f"((c)[3])   \
                 : "r"((a)[0]), "r"((a)[1]), "r"((a)[2]), "r"((a)[3]),      \
                   "r"(b0), "r"(b1), "f"(zr))

// ---------------- branchless sorted-3 insert (5 FMNMX, no indices) --------
__device__ __forceinline__ void ins3(float &a, float &b, float &c, float x) {
    float m;
    m = fmaxf(a, x); x = fminf(a, x); a = m;
    m = fmaxf(b, x); x = fminf(b, x); b = m;
    c = fmaxf(c, x);
}

// ---------------- top-8 (value,idx) helpers for the endgame merge ----------
__device__ __forceinline__ void t8_ins(float (&tv)[K8], int (&ti)[K8], float s, int idx) {
    tv[K8 - 1] = s; ti[K8 - 1] = idx;
    #pragma unroll
    for (int p = K8 - 1; p > 0; --p) {
        if (tv[p] > tv[p - 1]) {
            float fv = tv[p]; tv[p] = tv[p - 1]; tv[p - 1] = fv;
            int fi = ti[p]; ti[p] = ti[p - 1]; ti[p - 1] = fi;
        }
    }
}
__device__ __forceinline__ void t8_merge_xor(float (&tv)[K8], int (&ti)[K8], int off) {
    float pv[K8]; int pi[K8];
    #pragma unroll
    for (int r = 0; r < K8; ++r) {
        pv[r] = __shfl_xor_sync(0xffffffffu, tv[r], off);
        pi[r] = __shfl_xor_sync(0xffffffffu, ti[r], off);
    }
    #pragma unroll
    for (int r = 0; r < K8; ++r)
        if (pv[r] > tv[K8 - 1]) t8_ins(tv, ti, pv[r], pi[r]);
}

// ---------------- kernel: fused query prep + exclude decode ----------------
__global__ void prep_all(const float* __restrict__ q, const void* __restrict__ ex,
                         int B) {
    if (blockIdx.x < (unsigned)(B / 8)) {
        int w = blockIdx.x * 8 + (threadIdx.x >> 5);
        int lane = threadIdx.x & 31;
        float4 v = *(const float4*)(q + (size_t)w * DIM + lane * 4);
        float ss = v.x * v.x + v.y * v.y + v.z * v.z + v.w * v.w;
        #pragma unroll
        for (int o = 16; o; o >>= 1) ss += __shfl_xor_sync(0xffffffffu, ss, o);
        float sc = 1.0f / fmaxf(sqrtf(ss), 1e-12f);
        float4 r = make_float4(v.x * sc, v.y * sc, v.z * sc, v.w * sc);
        size_t off = (size_t)w * DIM + lane * 4;
        *(float4*)(g_qn + off) = r;
        __nv_bfloat162 h0 = __floats2bfloat162_rn(r.x, r.y);
        __nv_bfloat162 h1 = __floats2bfloat162_rn(r.z, r.w);
        *(uint2*)(g_qh + off) = make_uint2(*(uint32_t*)&h0, *(uint32_t*)&h1);
    } else {
        // exclude decode: int32 vs int64 sniff
        __shared__ int nz;
        int t = threadIdx.x;
        if (t == 0) nz = 0;
        __syncthreads();
        const int* e32 = (const int*)ex;
        for (int i = t; i < B / 2; i += blockDim.x)
            if (e32[2 * i + 1] != 0) atomicAdd(&nz, 1);
        __syncthreads();
        bool is64 = (nz == 0);
        for (int i = t; i < B; i += blockDim.x) {
            long long v = is64 ? ((const long long*)ex)[i] : (long long)e32[i];
            g_excl[i] = (int)v;
        }
    }
}

// ---------------- kernel: fp32 memory -> bf16 hi ----------------
__global__ void split_mem(const float* __restrict__ mem, int N, int NPAD) {
    int total4 = NPAD * (DIM / 4);
    for (int i = blockIdx.x * blockDim.x + threadIdx.x; i < total4;
         i += gridDim.x * blockDim.x) {
        int row = i >> 5;
        float4 v = make_float4(0.f, 0.f, 0.f, 0.f);
        if (row < N) v = ((const float4*)mem)[i];
        __nv_bfloat162 h0 = __floats2bfloat162_rn(v.x, v.y);
        __nv_bfloat162 h1 = __floats2bfloat162_rn(v.z, v.w);
        ((uint2*)g_kh)[i] = make_uint2(*(uint32_t*)&h0, *(uint32_t*)&h1);
    }
}

// ---------------- key tile loader (XOR-swizzled rows for ldmatrix) ----------
__device__ __forceinline__ void load_ktile(uint32_t stage_u, int key0, bool valid, int tid) {
    if (valid) {
        #pragma unroll
        for (int c = tid; c < 2048; c += 512) {
            int row = c >> 4, ch = c & 15;
            uint32_t off = (uint32_t)(row * 256 + (((ch ^ (row & 7))) << 4));
            cp16(stage_u + off, g_kh + (size_t)(key0 + row) * DIM + ch * 8);
        }
    }
    CP_COMMIT();
}

// ---------------- MMA group: 16 q-rows x 2 m-blocks, 16 keys (one nbp) ------
// addr(kc) = lbase + (32*kc ^ rh16); lbase = st + kb256 + rl16 + nbp*4096
#define MMA_GROUP(acc, st, nbpv)                                            \
    do {                                                                    \
        uint32_t lbase = (st) + (uint32_t)kb256 + rl16 + (uint32_t)(nbpv) * 4096u; \
        _Pragma("unroll")                                                   \
        for (int kc = 0; kc < 8; ++kc) {                                    \
            uint32_t bh0, bh1, bh2, bh3;                                    \
            LDSM4(bh0, bh1, bh2, bh3, lbase + ((uint32_t)(32 * kc) ^ rh16)); \
            if (kc == 0) {                                                  \
                MMA16816_Z(acc[0][0], (&ah[kc][0]), bh0, bh1, fzero);       \
                MMA16816_Z(acc[0][1], (&ah[kc][0]), bh2, bh3, fzero);       \
                MMA16816_Z(acc[1][0], (&ah[kc][4]), bh0, bh1, fzero);       \
                MMA16816_Z(acc[1][1], (&ah[kc][4]), bh2, bh3, fzero);       \
            } else {                                                        \
                MMA16816(acc[0][0], (&ah[kc][0]), bh0, bh1);                \
                MMA16816(acc[0][1], (&ah[kc][0]), bh2, bh3);                \
                MMA16816(acc[1][0], (&ah[kc][4]), bh0, bh1);                \
                MMA16816(acc[1][1], (&ah[kc][4]), bh2, bh3);                \
            }                                                               \
        }                                                                   \
    } while (0)

// scan one group's 16 values; meta base = 4*g (g = half-tile group index)
#define SCAN_GROUP(acc, gval)                                               \
    do {                                                                    \
        uint32_t tb = (uint32_t)(gval) << 2;                                \
        _Pragma("unroll")                                                   \
        for (int m = 0; m < 2; ++m) {                                       \
            _Pragma("unroll")                                               \
            for (int n = 0; n < 2; ++n) {                                   \
                uint32_t meta = tb | ((uint32_t)n << 1);                    \
                uint32_t s0, s1;                                            \
                s0 = (__float_as_uint(acc[m][n][0]) & 0xFFFFFC00u) | meta;  \
                s1 = (__float_as_uint(acc[m][n][1]) & 0xFFFFFC00u) | meta | 1u; \
                ins3(lv[m * 2][0], lv[m * 2][1], lv[m * 2][2],              \
                     fmaxf(__uint_as_float(s0), __uint_as_float(s1)));      \
                s0 = (__float_as_uint(acc[m][n][2]) & 0xFFFFFC00u) | meta;  \
                s1 = (__float_as_uint(acc[m][n][3]) & 0xFFFFFC00u) | meta | 1u; \
                ins3(lv[m * 2 + 1][0], lv[m * 2 + 1][1], lv[m * 2 + 1][2],  \
                     fmaxf(__uint_as_float(s0), __uint_as_float(s1)));      \
            }                                                               \
        }                                                                   \
    } while (0)

// ---------------- main filter kernel ----------------
__global__ void __launch_bounds__(512, 1)
sim_topk(int N, int Ntiles) {
    extern __shared__ __align__(16) char sm[];
    uint32_t smb = smem_u32(sm);
    uint32_t stage_u = (smb + 1023u) & ~1023u;

    int tid = threadIdx.x;
    int wid = tid >> 5;
    int lane = tid & 31;
    int wq = wid & 3;            // query-row group (32 rows)
    int kq = wid >> 2;           // key quarter (32 keys)
    int qbase = blockIdx.x * 128;
    int chunk = blockIdx.y;

    int TPC = (Ntiles + NCHUNKS - 1) / NCHUNKS;   // 87
    int t0 = chunk * TPC;
    int T = min(TPC, Ntiles - t0); if (T < 0) T = 0;

    load_ktile(stage_u,         (t0 + 0) * 128, 0 < T, tid);
    load_ktile(stage_u + 32768, (t0 + 1) * 128, 1 < T, tid);

    // preload A fragments: this warp's 32 query rows = 2 m16 blocks
    int qr = qbase + wq * 32 + (lane >> 2);
    uint32_t ah[8][8];           // [kc][m*4 + j]
    #pragma unroll
    for (int kc = 0; kc < 8; ++kc) {
        int c = kc * 16 + (lane & 3) * 2;
        #pragma unroll
        for (int m = 0; m < 2; ++m) {
            const __nv_bfloat16* qp = g_qh + (size_t)(qr + m * 16) * DIM;
            ah[kc][m * 4 + 0] = *(const uint32_t*)(qp + c);
            ah[kc][m * 4 + 1] = *(const uint32_t*)(qp + 8 * DIM + c);
            ah[kc][m * 4 + 2] = *(const uint32_t*)(qp + c + 8);
            ah[kc][m * 4 + 3] = *(const uint32_t*)(qp + 8 * DIM + c + 8);
        }
    }

    // 4 per-lane top-3 lists (rows +0,+8,+16,+24), idx packed in low 10 bits
    float lv[4][3];
    #pragma unroll
    for (int l = 0; l < 4; ++l)
        lv[l][0] = lv[l][1] = lv[l][2] = -3.0e38f;

    int r_   = lane & 7;
    int cbit = (lane >> 3) & 1;
    int kb256 = (kq << 13) + ((lane >> 4) * 8 + r_) * 256;
    uint32_t rl16 = (uint32_t)((cbit ^ (r_ & 1)) << 4);
    uint32_t rh16 = (uint32_t)((r_ & 6) << 4);

    uint32_t stA = stage_u, stB = stage_u + 32768, stC = stage_u + 65536;
    const float fzero = 0.0f;

    float accA[2][2][4], accB[2][2][4];
    int G = 2 * T;

    if (T > 0) {
        // prologue: tile0 resident; prefetch tile2; issue group 0
        CP_WAIT(1);
        __syncthreads();
        load_ktile(stC, (t0 + 2) * 128, 2 < T, tid);
        MMA_GROUP(accA, stA, 0);

        int g = 0;
        while (true) {
            // ---- A-phase: issue group g+1 (same tile, nbp=1), scan accA(g)
            if (g + 1 < G)
                MMA_GROUP(accB, stA, 1);
            SCAN_GROUP(accA, g);
            if (++g >= G) break;

            // ---- B-phase: issue group g+1 (new tile, nbp=0), scan accB(g)
            if (g + 1 < G) {
                uint32_t tmp = stA; stA = stB; stB = stC; stC = tmp;
                CP_WAIT(1);
                __syncthreads();
                int tn = (g + 1) >> 1;
                load_ktile(stC, (t0 + tn + 2) * 128, (tn + 2) < T, tid);
                MMA_GROUP(accA, stA, 0);
            }
            SCAN_GROUP(accB, g);
            if (++g >= G) break;
        }
    }

    CP_WAIT(0);

    // ---- decode packed candidates, merge across the 4 lanes per row ----
    int cb = kq * 32 + (lane & 3) * 2;   // key base within tile
    #pragma unroll
    for (int l = 0; l < 4; ++l) {
        float tv[K8]; int ti[K8];
        #pragma unroll
        for (int r = 0; r < 3; ++r) {
            uint32_t u = __float_as_uint(lv[l][r]);
            int gg = (int)((u >> 2) & 0xFF);
            ti[r] = (t0 + (gg >> 1)) * 128 + cb +
                    (gg & 1) * 16 + (int)((u >> 1) & 1) * 8 + (int)(u & 1);
            tv[r] = lv[l][r];
        }
        #pragma unroll
        for (int r = 3; r < K8; ++r) { tv[r] = -INFINITY; ti[r] = -1; }

        t8_merge_xor(tv, ti, 1);
        t8_merge_xor(tv, ti, 2);

        if ((lane & 3) == 0) {
            int row = wq * 32 + (lane >> 2) + l * 8;
            size_t slotbase = (size_t)((blockIdx.x * NCHUNKS + chunk) * 4 + kq) * 128;
            size_t b = (slotbase + row) * PK;
            #pragma unroll
            for (int r = 0; r < PK; ++r) { g_pval[b + r] = tv[r]; g_pidx[b + r] = ti[r]; }
        }
    }
}

// ---------------- merge + exact rescore + softmax/gather/normalize ----------
__global__ void merge_out(const float* __restrict__ mem, float* __restrict__ out,
                          int N, int B) {
    int q = (blockIdx.x * blockDim.x + threadIdx.x) >> 5;
    int lane = threadIdx.x & 31;
    if (q >= B) return;
    int qtile = q >> 7, ql = q & 127;
    int exq = g_excl[q];

    // ---- phase 1: approx top-RESC of 288 candidates (9 per lane),
    // filtering pad keys (ci >= N) and the exclude index here.
    float cv[9]; int ci[9];
    #pragma unroll
    for (int s = 0; s < 9; ++s) {
        int cidx = lane + 32 * s;                       // < 288 always
        int c = cidx >> 2, r = cidx & 3;
        size_t base = ((size_t)(qtile * NSLOTS + c) * 128 + ql) * PK + r;
        float v = g_pval[base]; int id = g_pidx[base];
        if ((unsigned)id >= (unsigned)N || id == exq) v = -INFINITY;
        cv[s] = v; ci[s] = id;
    }

    int ridx[RESC];
    #pragma unroll
    for (int k = 0; k < RESC; ++k) {
        float bv = cv[0]; int bi = ci[0];
        #pragma unroll
        for (int s = 1; s < 9; ++s)
            if (cv[s] > bv || (cv[s] == bv && ci[s] < bi)) { bv = cv[s]; bi = ci[s]; }
        #pragma unroll
        for (int o = 16; o; o >>= 1) {
            float ov = __shfl_xor_sync(0xffffffffu, bv, o);
            int   oi = __shfl_xor_sync(0xffffffffu, bi, o);
            if (ov > bv || (ov == bv && oi < bi)) { bv = ov; bi = oi; }
        }
        ridx[k] = (bi < 0 || bi >= N) ? 0 : bi;   // safety clamp
        #pragma unroll
        for (int s = 0; s < 9; ++s) if (ci[s] == bi) cv[s] = -INFINITY;
    }

    // ---- phase 2: exact fp32 rescore of the RESC survivors
    float4 qv = *(const float4*)(g_qn + (size_t)q * DIM + lane * 4);
    float rv[RESC];
    #pragma unroll
    for (int k = 0; k < RESC; ++k) {
        float4 m4 = *(const float4*)(mem + (size_t)ridx[k] * DIM + lane * 4);
        float d = qv.x * m4.x + qv.y * m4.y + qv.z * m4.z + qv.w * m4.w;
        #pragma unroll
        for (int o = 16; o; o >>= 1) d += __shfl_xor_sync(0xffffffffu, d, o);
        rv[k] = d;
    }

    // ---- phase 3: exact top-5 (lower index wins ties), all lanes redundant
    float tv[TOPK]; int ti[TOPK];
    int usedmask = 0;
    #pragma unroll
    for (int k = 0; k < TOPK; ++k) {
        float bv = -INFINITY; int bi = 0x7fffffff, bs = -1;
        #pragma unroll
        for (int r = 0; r < RESC; ++r)
            if (!((usedmask >> r) & 1) &&
                (rv[r] > bv || (rv[r] == bv && ridx[r] < bi))) {
                bv = rv[r]; bi = ridx[r]; bs = r;
            }
        usedmask |= 1 << bs;
        tv[k] = bv; ti[k] = bi;
    }

    // ---- softmax over exact top sims
    float e[TOPK], ssum = 0.f;
    #pragma unroll
    for (int k = 0; k < TOPK; ++k) { e[k] = expf((tv[k] - tv[0]) * INV_T); ssum += e[k]; }
    float w[TOPK];
    #pragma unroll
    for (int k = 0; k < TOPK; ++k) w[k] = e[k] / ssum;

    // ---- weighted gather + renormalize
    int d0 = lane * 4;
    float4 a = make_float4(0.f, 0.f, 0.f, 0.f);
    #pragma unroll
    for (int k = 0; k < TOPK; ++k) {
        float4 m4 = *(const float4*)(mem + (size_t)ti[k] * DIM + d0);
        a.x += w[k] * m4.x; a.y += w[k] * m4.y; a.z += w[k] * m4.z; a.w += w[k] * m4.w;
    }
    float ss = a.x * a.x + a.y * a.y + a.z * a.z + a.w * a.w;
    #pragma unroll
    for (int o = 16; o; o >>= 1) ss += __shfl_xor_sync(0xffffffffu, ss, o);
    float sc = 1.0f / fmaxf(sqrtf(ss), 1e-12f);
    float4 r4 = make_float4(a.x * sc, a.y * sc, a.z * sc, a.w * sc);
    *(float4*)(out + (size_t)q * DIM + d0) = r4;

    if (lane == 0) {
        out[(size_t)B * DIM + q] = 1.0f - tv[0];
        #pragma unroll
        for (int k = 0; k < TOPK; ++k)
            out[(size_t)B * DIM + B + (size_t)q * TOPK + k] = w[k];
    }
}

// ---------------- launch ----------------
extern "C" void kernel_launch(void* const* d_in, const int* in_sizes, int n_in,
                              void* d_out, int out_size) {
    const float* query  = (const float*)d_in[0];
    const float* memory = (const float*)d_in[1];
    const void*  excl   = d_in[3];
    int B = in_sizes[0] / DIM;              // 1024
    int N = in_sizes[1] / DIM;              // 200000
    int Ntiles = (N + 127) / 128;           // 1563
    int NPAD = Ntiles * 128;
    float* out = (float*)d_out;

    prep_all<<<B / 8 + 1, 256>>>(query, excl, B);
    split_mem<<<2048, 256>>>(memory, N, NPAD);

    const int SMEM = 3 * 32768 + 1024;      // 99,328 B
    cudaFuncSetAttribute(sim_topk, cudaFuncAttributeMaxDynamicSharedMemorySize, SMEM);
    sim_topk<<<dim3(B / 128, NCHUNKS), 512, SMEM>>>(N, Ntiles);

    merge_out<<<(B * 32 + 255) / 256, 256>>>(memory, out, N, B);
}

// round 12
// speedup vs baseline: 1.1069x; 1.1069x over previous
#include <cuda_runtime.h>
#include <cuda_bf16.h>
#include <math.h>
#include <stdint.h>

// ---------------- problem constants ----------------
#define MAXB     1024
#define DIM      128
#define NSLICE   36                 // key slices (grid.y)
#define NSLOTS   (NSLICE * 2)       // per-slice key-halves
#define PK       4                  // stored candidate depth per slot
#define K8       8                  // merge list depth
#define TOPK     5
#define RESC     10                 // rescored candidates per query
#define INV_T    10.0f
#define NPADMAX  (3128 * 64)

// ---------------- device scratch ----------------
__device__ int   g_excl[MAXB];
__device__ float g_qn[MAXB * DIM];                       // normalized queries fp32
__device__ float g_pval[8 * NSLOTS * 128 * PK];
__device__ int   g_pidx[8 * NSLOTS * 128 * PK];
__device__ __nv_bfloat16 g_qh[MAXB * DIM];
__device__ __nv_bfloat16 g_kh[(size_t)NPADMAX * DIM];    // 51.2 MB

// ---------------- PTX helpers ----------------
__device__ __forceinline__ uint32_t smem_u32(const void* p) {
    uint32_t a;
    asm("{ .reg .u64 t; cvta.to.shared.u64 t, %1; cvt.u32.u64 %0, t; }" : "=r"(a) : "l"(p));
    return a;
}
__device__ __forceinline__ void cp16(uint32_t s, const void* g) {
    asm volatile("cp.async.cg.shared.global [%0], [%1], 16;" :: "r"(s), "l"(g));
}
#define CP_COMMIT()  asm volatile("cp.async.commit_group;")
#define CP_WAIT(n)   asm volatile("cp.async.wait_group %0;" :: "n"(n))

#define LDSM4(r0, r1, r2, r3, addr)                                         \
    asm volatile("ldmatrix.sync.aligned.m8n8.x4.shared.b16 {%0,%1,%2,%3}, [%4];" \
                 : "=r"(r0), "=r"(r1), "=r"(r2), "=r"(r3) : "r"(addr))

#define MMA16816(c, a, b0, b1)                                              \
    asm volatile("mma.sync.aligned.m16n8k16.row.col.f32.bf16.bf16.f32 "     \
                 "{%0,%1,%2,%3},{%4,%5,%6,%7},{%8,%9},{%0,%1,%2,%3};"       \
                 : "+f"((c)[0]), "+f"((c)[1]), "+f"((c)[2]), "+f"((c)[3])   \
                 : "r"((a)[0]), "r"((a)[1]), "r"((a)[2]), "r"((a)[3]),      \
                   "r"(b0), "r"(b1))

// first-k MMA: D = A*B + 0 (separate zero C input; kills acc-init MOVs)
#define MMA16816_Z(c, a, b0, b1, zr)                                        \
    asm volatile("mma.sync.aligned.m16n8k16.row.col.f32.bf16.bf16.f32 "     \
                 "{%0,%1,%2,%3},{%4,%5,%6,%7},{%8,%9},{%10,%10,%10,%10};"   \
                 : "=f"((c)[0]), "=f"((c)[1]), "=f"((c)[2]), "=f"((c)[3])   \
                 : "r"((a)[0]), "r"((a)[1]), "r"((a)[2]), "r"((a)[3]),      \
                   "r"(b0), "r"(b1), "f"(zr))

// ---------------- branchless sorted-3 insert (5 FMNMX, no indices) --------
__device__ __forceinline__ void ins3(float &a, float &b, float &c, float x) {
    float m;
    m = fmaxf(a, x); x = fminf(a, x); a = m;
    m = fmaxf(b, x); x = fminf(b, x); b = m;
    c = fmaxf(c, x);
}

// ---------------- top-8 (value,idx) helpers for the endgame merge ----------
__device__ __forceinline__ void t8_ins(float (&tv)[K8], int (&ti)[K8], float s, int idx) {
    tv[K8 - 1] = s; ti[K8 - 1] = idx;
    #pragma unroll
    for (int p = K8 - 1; p > 0; --p) {
        if (tv[p] > tv[p - 1]) {
            float fv = tv[p]; tv[p] = tv[p - 1]; tv[p - 1] = fv;
            int fi = ti[p]; ti[p] = ti[p - 1]; ti[p - 1] = fi;
        }
    }
}
__device__ __forceinline__ void t8_merge_xor(float (&tv)[K8], int (&ti)[K8], int off) {
    float pv[K8]; int pi[K8];
    #pragma unroll
    for (int r = 0; r < K8; ++r) {
        pv[r] = __shfl_xor_sync(0xffffffffu, tv[r], off);
        pi[r] = __shfl_xor_sync(0xffffffffu, ti[r], off);
    }
    #pragma unroll
    for (int r = 0; r < K8; ++r)
        if (pv[r] > tv[K8 - 1]) t8_ins(tv, ti, pv[r], pi[r]);
}

// ---------------- kernel: fused query prep + exclude decode ----------------
__global__ void prep_all(const float* __restrict__ q, const void* __restrict__ ex,
                         int B) {
    if (blockIdx.x < (unsigned)(B / 8)) {
        int w = blockIdx.x * 8 + (threadIdx.x >> 5);
        int lane = threadIdx.x & 31;
        float4 v = *(const float4*)(q + (size_t)w * DIM + lane * 4);
        float ss = v.x * v.x + v.y * v.y + v.z * v.z + v.w * v.w;
        #pragma unroll
        for (int o = 16; o; o >>= 1) ss += __shfl_xor_sync(0xffffffffu, ss, o);
        float sc = 1.0f / fmaxf(sqrtf(ss), 1e-12f);
        float4 r = make_float4(v.x * sc, v.y * sc, v.z * sc, v.w * sc);
        size_t off = (size_t)w * DIM + lane * 4;
        *(float4*)(g_qn + off) = r;
        __nv_bfloat162 h0 = __floats2bfloat162_rn(r.x, r.y);
        __nv_bfloat162 h1 = __floats2bfloat162_rn(r.z, r.w);
        *(uint2*)(g_qh + off) = make_uint2(*(uint32_t*)&h0, *(uint32_t*)&h1);
    } else {
        // exclude decode: int32 vs int64 sniff
        __shared__ int nz;
        int t = threadIdx.x;
        if (t == 0) nz = 0;
        __syncthreads();
        const int* e32 = (const int*)ex;
        for (int i = t; i < B / 2; i += blockDim.x)
            if (e32[2 * i + 1] != 0) atomicAdd(&nz, 1);
        __syncthreads();
        bool is64 = (nz == 0);
        for (int i = t; i < B; i += blockDim.x) {
            long long v = is64 ? ((const long long*)ex)[i] : (long long)e32[i];
            g_excl[i] = (int)v;
        }
    }
}

// ---------------- kernel: fp32 memory -> bf16 hi ----------------
__global__ void split_mem(const float* __restrict__ mem, int N, int NPAD) {
    int total4 = NPAD * (DIM / 4);
    for (int i = blockIdx.x * blockDim.x + threadIdx.x; i < total4;
         i += gridDim.x * blockDim.x) {
        int row = i >> 5;
        float4 v = make_float4(0.f, 0.f, 0.f, 0.f);
        if (row < N) v = ((const float4*)mem)[i];
        __nv_bfloat162 h0 = __floats2bfloat162_rn(v.x, v.y);
        __nv_bfloat162 h1 = __floats2bfloat162_rn(v.z, v.w);
        ((uint2*)g_kh)[i] = make_uint2(*(uint32_t*)&h0, *(uint32_t*)&h1);
    }
}

// ---------------- key tile loader: 64 keys x 256B, XOR-swizzled ------------
__device__ __forceinline__ void load_ktile(uint32_t stage_u, int key0, bool valid, int tid) {
    if (valid) {
        #pragma unroll
        for (int c = tid; c < 1024; c += 256) {
            int row = c >> 4, ch = c & 15;
            uint32_t off = (uint32_t)(row * 256 + (((ch ^ (row & 7))) << 4));
            cp16(stage_u + off, g_kh + (size_t)(key0 + row) * DIM + ch * 8);
        }
    }
    CP_COMMIT();
}

// ---------------- main filter kernel: 256 threads, 2 CTAs/SM ---------------
__global__ void __launch_bounds__(256, 2)
sim_topk(int N, int Ntiles) {
    extern __shared__ __align__(16) char sm[];
    uint32_t smb = smem_u32(sm);
    uint32_t stage_u = (smb + 1023u) & ~1023u;

    int tid = threadIdx.x;
    int wid = tid >> 5;
    int lane = tid & 31;
    int wq = wid & 3;            // query-row group (32 rows)
    int kq = wid >> 2;           // key half (32 of the 64 tile keys)
    int qbase = blockIdx.x * 128;
    int slice = blockIdx.y;

    int TPC = (Ntiles + NSLICE - 1) / NSLICE;     // 87 (< 128, fits 7 bits)
    int t0 = slice * TPC;
    int T = min(TPC, Ntiles - t0); if (T < 0) T = 0;

    load_ktile(stage_u,         (t0 + 0) * 64, 0 < T, tid);
    load_ktile(stage_u + 16384, (t0 + 1) * 64, 1 < T, tid);

    // preload A fragments: this warp's 32 query rows = 2 m16 blocks
    int qr = qbase + wq * 32 + (lane >> 2);
    uint32_t ah[8][8];           // [kc][m*4 + j]
    #pragma unroll
    for (int kc = 0; kc < 8; ++kc) {
        int c = kc * 16 + (lane & 3) * 2;
        #pragma unroll
        for (int m = 0; m < 2; ++m) {
            const __nv_bfloat16* qp = g_qh + (size_t)(qr + m * 16) * DIM;
            ah[kc][m * 4 + 0] = *(const uint32_t*)(qp + c);
            ah[kc][m * 4 + 1] = *(const uint32_t*)(qp + 8 * DIM + c);
            ah[kc][m * 4 + 2] = *(const uint32_t*)(qp + c + 8);
            ah[kc][m * 4 + 3] = *(const uint32_t*)(qp + 8 * DIM + c + 8);
        }
    }

    // 4 per-lane top-3 lists (rows +0,+8,+16,+24), idx packed in low 10 bits
    float lv[4][3];
    #pragma unroll
    for (int l = 0; l < 4; ++l)
        lv[l][0] = lv[l][1] = lv[l][2] = -3.0e38f;

    int r_   = lane & 7;
    int cbit = (lane >> 3) & 1;
    int kb256 = (kq << 13) + ((lane >> 4) * 8 + r_) * 256;

    // precompute swizzled LDSM offsets (constant across tiles)
    uint32_t off_h[8];
    #pragma unroll
    for (int kc = 0; kc < 8; ++kc)
        off_h[kc] = (uint32_t)kb256 + (uint32_t)(((kc * 2 + cbit) ^ r_) << 4);

    uint32_t stA = stage_u, stB = stage_u + 16384, stC = stage_u + 32768;
    const float fzero = 0.0f;

    for (int t = 0; t < T; ++t) {
        CP_WAIT(1);
        __syncthreads();

        load_ktile(stC, (t0 + t + 2) * 64, (t + 2) < T, tid);

        #pragma unroll
        for (int nbp = 0; nbp < 2; ++nbp) {
            float acc[2][2][4];              // [m][n][j]
            #pragma unroll
            for (int kc = 0; kc < 8; ++kc) {
                uint32_t bh0, bh1, bh2, bh3;
                LDSM4(bh0, bh1, bh2, bh3, stA + off_h[kc] + nbp * 4096);
                if (kc == 0) {
                    MMA16816_Z(acc[0][0], (&ah[kc][0]), bh0, bh1, fzero);
                    MMA16816_Z(acc[0][1], (&ah[kc][0]), bh2, bh3, fzero);
                    MMA16816_Z(acc[1][0], (&ah[kc][4]), bh0, bh1, fzero);
                    MMA16816_Z(acc[1][1], (&ah[kc][4]), bh2, bh3, fzero);
                } else {
                    MMA16816(acc[0][0], (&ah[kc][0]), bh0, bh1);
                    MMA16816(acc[0][1], (&ah[kc][0]), bh2, bh3);
                    MMA16816(acc[1][0], (&ah[kc][4]), bh0, bh1);
                    MMA16816(acc[1][1], (&ah[kc][4]), bh2, bh3);
                }
            }

            // scan these 16 values now (pair-max + sorted-3 insert)
            uint32_t tb = ((uint32_t)t << 3) | ((uint32_t)nbp << 2);
            #pragma unroll
            for (int m = 0; m < 2; ++m) {
                #pragma unroll
                for (int n = 0; n < 2; ++n) {
                    uint32_t meta = tb | ((uint32_t)n << 1);
                    uint32_t s0, s1;
                    s0 = (__float_as_uint(acc[m][n][0]) & 0xFFFFFC00u) | meta;
                    s1 = (__float_as_uint(acc[m][n][1]) & 0xFFFFFC00u) | meta | 1u;
                    ins3(lv[m * 2][0], lv[m * 2][1], lv[m * 2][2],
                         fmaxf(__uint_as_float(s0), __uint_as_float(s1)));
                    s0 = (__float_as_uint(acc[m][n][2]) & 0xFFFFFC00u) | meta;
                    s1 = (__float_as_uint(acc[m][n][3]) & 0xFFFFFC00u) | meta | 1u;
                    ins3(lv[m * 2 + 1][0], lv[m * 2 + 1][1], lv[m * 2 + 1][2],
                         fmaxf(__uint_as_float(s0), __uint_as_float(s1)));
                }
            }
        }

        uint32_t tmp = stA; stA = stB; stB = stC; stC = tmp;
    }

    CP_WAIT(0);

    // ---- decode packed candidates, merge across the 4 lanes per row ----
    int cb = kq * 32 + (lane & 3) * 2;   // key base within 64-key tile
    #pragma unroll
    for (int l = 0; l < 4; ++l) {
        float tv[K8]; int ti[K8];
        #pragma unroll
        for (int r = 0; r < 3; ++r) {
            uint32_t u = __float_as_uint(lv[l][r]);
            tv[r] = lv[l][r];
            ti[r] = (t0 + (int)((u >> 3) & 0x7F)) * 64 + cb +
                    (int)((u >> 2) & 1) * 16 + (int)((u >> 1) & 1) * 8 + (int)(u & 1);
        }
        #pragma unroll
        for (int r = 3; r < K8; ++r) { tv[r] = -INFINITY; ti[r] = -1; }

        t8_merge_xor(tv, ti, 1);
        t8_merge_xor(tv, ti, 2);

        if ((lane & 3) == 0) {
            int row = wq * 32 + (lane >> 2) + l * 8;
            size_t slotbase = (size_t)((blockIdx.x * NSLICE + slice) * 2 + kq) * 128;
            size_t b = (slotbase + row) * PK;
            #pragma unroll
            for (int r = 0; r < PK; ++r) { g_pval[b + r] = tv[r]; g_pidx[b + r] = ti[r]; }
        }
    }
}

// ---------------- merge + exact rescore + softmax/gather/normalize ----------
__global__ void merge_out(const float* __restrict__ mem, float* __restrict__ out,
                          int N, int B) {
    int q = (blockIdx.x * blockDim.x + threadIdx.x) >> 5;
    int lane = threadIdx.x & 31;
    if (q >= B) return;
    int qtile = q >> 7, ql = q & 127;
    int exq = g_excl[q];

    // ---- phase 1: approx top-RESC of 288 candidates (9 per lane),
    // filtering pad keys (ci >= N) and the exclude index here.
    float cv[9]; int ci[9];
    #pragma unroll
    for (int s = 0; s < 9; ++s) {
        int cidx = lane + 32 * s;                       // < 288 always
        int c = cidx >> 2, r = cidx & 3;
        size_t base = ((size_t)(qtile * NSLOTS + c) * 128 + ql) * PK + r;
        float v = g_pval[base]; int id = g_pidx[base];
        if ((unsigned)id >= (unsigned)N || id == exq) v = -INFINITY;
        cv[s] = v; ci[s] = id;
    }

    int ridx[RESC];
    #pragma unroll
    for (int k = 0; k < RESC; ++k) {
        float bv = cv[0]; int bi = ci[0];
        #pragma unroll
        for (int s = 1; s < 9; ++s)
            if (cv[s] > bv || (cv[s] == bv && ci[s] < bi)) { bv = cv[s]; bi = ci[s]; }
        #pragma unroll
        for (int o = 16; o; o >>= 1) {
            float ov = __shfl_xor_sync(0xffffffffu, bv, o);
            int   oi = __shfl_xor_sync(0xffffffffu, bi, o);
            if (ov > bv || (ov == bv && oi < bi)) { bv = ov; bi = oi; }
        }
        ridx[k] = (bi < 0 || bi >= N) ? 0 : bi;   // safety clamp
        #pragma unroll
        for (int s = 0; s < 9; ++s) if (ci[s] == bi) cv[s] = -INFINITY;
    }

    // ---- phase 2: exact fp32 rescore of the RESC survivors
    float4 qv = *(const float4*)(g_qn + (size_t)q * DIM + lane * 4);
    float rv[RESC];
    #pragma unroll
    for (int k = 0; k < RESC; ++k) {
        float4 m4 = *(const float4*)(mem + (size_t)ridx[k] * DIM + lane * 4);
        float d = qv.x * m4.x + qv.y * m4.y + qv.z * m4.z + qv.w * m4.w;
        #pragma unroll
        for (int o = 16; o; o >>= 1) d += __shfl_xor_sync(0xffffffffu, d, o);
        rv[k] = d;
    }

    // ---- phase 3: exact top-5 (lower index wins ties), all lanes redundant
    float tv[TOPK]; int ti[TOPK];
    int usedmask = 0;
    #pragma unroll
    for (int k = 0; k < TOPK; ++k) {
        float bv = -INFINITY; int bi = 0x7fffffff, bs = -1;
        #pragma unroll
        for (int r = 0; r < RESC; ++r)
            if (!((usedmask >> r) & 1) &&
                (rv[r] > bv || (rv[r] == bv && ridx[r] < bi))) {
                bv = rv[r]; bi = ridx[r]; bs = r;
            }
        usedmask |= 1 << bs;
        tv[k] = bv; ti[k] = bi;
    }

    // ---- softmax over exact top sims
    float e[TOPK], ssum = 0.f;
    #pragma unroll
    for (int k = 0; k < TOPK; ++k) { e[k] = expf((tv[k] - tv[0]) * INV_T); ssum += e[k]; }
    float w[TOPK];
    #pragma unroll
    for (int k = 0; k < TOPK; ++k) w[k] = e[k] / ssum;

    // ---- weighted gather + renormalize
    int d0 = lane * 4;
    float4 a = make_float4(0.f, 0.f, 0.f, 0.f);
    #pragma unroll
    for (int k = 0; k < TOPK; ++k) {
        float4 m4 = *(const float4*)(mem + (size_t)ti[k] * DIM + d0);
        a.x += w[k] * m4.x; a.y += w[k] * m4.y; a.z += w[k] * m4.z; a.w += w[k] * m4.w;
    }
    float ss = a.x * a.x + a.y * a.y + a.z * a.z + a.w * a.w;
    #pragma unroll
    for (int o = 16; o; o >>= 1) ss += __shfl_xor_sync(0xffffffffu, ss, o);
    float sc = 1.0f / fmaxf(sqrtf(ss), 1e-12f);
    float4 r4 = make_float4(a.x * sc, a.y * sc, a.z * sc, a.w * sc);
    *(float4*)(out + (size_t)q * DIM + d0) = r4;

    if (lane == 0) {
        out[(size_t)B * DIM + q] = 1.0f - tv[0];
        #pragma unroll
        for (int k = 0; k < TOPK; ++k)
            out[(size_t)B * DIM + B + (size_t)q * TOPK + k] = w[k];
    }
}

// ---------------- launch ----------------
extern "C" void kernel_launch(void* const* d_in, const int* in_sizes, int n_in,
                              void* d_out, int out_size) {
    const float* query  = (const float*)d_in[0];
    const float* memory = (const float*)d_in[1];
    const void*  excl   = d_in[3];
    int B = in_sizes[0] / DIM;              // 1024
    int N = in_sizes[1] / DIM;              // 200000
    int Ntiles = (N + 63) / 64;             // 3125 tiles of 64 keys
    int NPAD = Ntiles * 64;
    float* out = (float*)d_out;

    prep_all<<<B / 8 + 1, 256>>>(query, excl, B);
    split_mem<<<2048, 256>>>(memory, N, NPAD);

    const int SMEM = 3 * 16384 + 1024;      // 50,176 B per CTA (2 CTAs/SM)
    cudaFuncSetAttribute(sim_topk, cudaFuncAttributeMaxDynamicSharedMemorySize, SMEM);
    sim_topk<<<dim3(B / 128, NSLICE), 256, SMEM>>>(N, Ntiles);

    merge_out<<<(B * 32 + 255) / 256, 256>>>(memory, out, N, B);
}

// round 13
// speedup vs baseline: 1.1586x; 1.0467x over previous
#include <cuda_runtime.h>
#include <cuda_bf16.h>
#include <math.h>
#include <stdint.h>

// ---------------- problem constants ----------------
#define MAXB     1024
#define DIM      128
#define NSLICE   36                 // key slices (grid.y)
#define NSLOTS   (NSLICE * 2)       // per-slice key-halves
#define PK       4                  // stored candidate depth per slot
#define K8       8                  // merge list depth
#define TOPK     5
#define RESC     10                 // rescored quad candidates per query
#define INV_T    10.0f
#define NPADMAX  (3128 * 64)

// ---------------- device scratch ----------------
__device__ int   g_excl[MAXB];
__device__ float g_qn[MAXB * DIM];                       // normalized queries fp32
__device__ float g_pval[8 * NSLOTS * 128 * PK];
__device__ int   g_pidx[8 * NSLOTS * 128 * PK];
__device__ __nv_bfloat16 g_qh[MAXB * DIM];
__device__ __nv_bfloat16 g_kh[(size_t)NPADMAX * DIM];    // 51.2 MB

// ---------------- PTX helpers ----------------
__device__ __forceinline__ uint32_t smem_u32(const void* p) {
    uint32_t a;
    asm("{ .reg .u64 t; cvta.to.shared.u64 t, %1; cvt.u32.u64 %0, t; }" : "=r"(a) : "l"(p));
    return a;
}
__device__ __forceinline__ void cp16(uint32_t s, const void* g) {
    asm volatile("cp.async.cg.shared.global [%0], [%1], 16;" :: "r"(s), "l"(g));
}
#define CP_COMMIT()  asm volatile("cp.async.commit_group;")
#define CP_WAIT(n)   asm volatile("cp.async.wait_group %0;" :: "n"(n))

#define LDSM4(r0, r1, r2, r3, addr)                                         \
    asm volatile("ldmatrix.sync.aligned.m8n8.x4.shared.b16 {%0,%1,%2,%3}, [%4];" \
                 : "=r"(r0), "=r"(r1), "=r"(r2), "=r"(r3) : "r"(addr))

#define MMA16816(c, a, b0, b1)                                              \
    asm volatile("mma.sync.aligned.m16n8k16.row.col.f32.bf16.bf16.f32 "     \
                 "{%0,%1,%2,%3},{%4,%5,%6,%7},{%8,%9},{%0,%1,%2,%3};"       \
                 : "+f"((c)[0]), "+f"((c)[1]), "+f"((c)[2]), "+f"((c)[3])   \
                 : "r"((a)[0]), "r"((a)[1]), "r"((a)[2]), "r"((a)[3]),      \
                   "r"(b0), "r"(b1))

// first-k MMA: D = A*B + 0 (separate zero C input; kills acc-init MOVs)
#define MMA16816_Z(c, a, b0, b1, zr)                                        \
    asm volatile("mma.sync.aligned.m16n8k16.row.col.f32.bf16.bf16.f32 "     \
                 "{%0,%1,%2,%3},{%4,%5,%6,%7},{%8,%9},{%10,%10,%10,%10};"   \
                 : "=f"((c)[0]), "=f"((c)[1]), "=f"((c)[2]), "=f"((c)[3])   \
                 : "r"((a)[0]), "r"((a)[1]), "r"((a)[2]), "r"((a)[3]),      \
                   "r"(b0), "r"(b1), "f"(zr))

// ---------------- branchless sorted-3 insert (5 FMNMX, no indices) --------
__device__ __forceinline__ void ins3(float &a, float &b, float &c, float x) {
    float m;
    m = fmaxf(a, x); x = fminf(a, x); a = m;
    m = fmaxf(b, x); x = fminf(b, x); b = m;
    c = fmaxf(c, x);
}

// ---------------- top-8 (value,idx) helpers for the endgame merge ----------
__device__ __forceinline__ void t8_ins(float (&tv)[K8], int (&ti)[K8], float s, int idx) {
    tv[K8 - 1] = s; ti[K8 - 1] = idx;
    #pragma unroll
    for (int p = K8 - 1; p > 0; --p) {
        if (tv[p] > tv[p - 1]) {
            float fv = tv[p]; tv[p] = tv[p - 1]; tv[p - 1] = fv;
            int fi = ti[p]; ti[p] = ti[p - 1]; ti[p - 1] = fi;
        }
    }
}
__device__ __forceinline__ void t8_merge_xor(float (&tv)[K8], int (&ti)[K8], int off) {
    float pv[K8]; int pi[K8];
    #pragma unroll
    for (int r = 0; r < K8; ++r) {
        pv[r] = __shfl_xor_sync(0xffffffffu, tv[r], off);
        pi[r] = __shfl_xor_sync(0xffffffffu, ti[r], off);
    }
    #pragma unroll
    for (int r = 0; r < K8; ++r)
        if (pv[r] > tv[K8 - 1]) t8_ins(tv, ti, pv[r], pi[r]);
}

// ---------------- kernel: fused query prep + exclude decode ----------------
__global__ void prep_all(const float* __restrict__ q, const void* __restrict__ ex,
                         int B) {
    if (blockIdx.x < (unsigned)(B / 8)) {
        int w = blockIdx.x * 8 + (threadIdx.x >> 5);
        int lane = threadIdx.x & 31;
        float4 v = *(const float4*)(q + (size_t)w * DIM + lane * 4);
        float ss = v.x * v.x + v.y * v.y + v.z * v.z + v.w * v.w;
        #pragma unroll
        for (int o = 16; o; o >>= 1) ss += __shfl_xor_sync(0xffffffffu, ss, o);
        float sc = 1.0f / fmaxf(sqrtf(ss), 1e-12f);
        float4 r = make_float4(v.x * sc, v.y * sc, v.z * sc, v.w * sc);
        size_t off = (size_t)w * DIM + lane * 4;
        *(float4*)(g_qn + off) = r;
        __nv_bfloat162 h0 = __floats2bfloat162_rn(r.x, r.y);
        __nv_bfloat162 h1 = __floats2bfloat162_rn(r.z, r.w);
        *(uint2*)(g_qh + off) = make_uint2(*(uint32_t*)&h0, *(uint32_t*)&h1);
    } else {
        // exclude decode: int32 vs int64 sniff
        __shared__ int nz;
        int t = threadIdx.x;
        if (t == 0) nz = 0;
        __syncthreads();
        const int* e32 = (const int*)ex;
        for (int i = t; i < B / 2; i += blockDim.x)
            if (e32[2 * i + 1] != 0) atomicAdd(&nz, 1);
        __syncthreads();
        bool is64 = (nz == 0);
        for (int i = t; i < B; i += blockDim.x) {
            long long v = is64 ? ((const long long*)ex)[i] : (long long)e32[i];
            g_excl[i] = (int)v;
        }
    }
}

// ---------------- kernel: fp32 memory -> bf16 hi ----------------
__global__ void split_mem(const float* __restrict__ mem, int N, int NPAD) {
    int total4 = NPAD * (DIM / 4);
    for (int i = blockIdx.x * blockDim.x + threadIdx.x; i < total4;
         i += gridDim.x * blockDim.x) {
        int row = i >> 5;
        float4 v = make_float4(0.f, 0.f, 0.f, 0.f);
        if (row < N) v = ((const float4*)mem)[i];
        __nv_bfloat162 h0 = __floats2bfloat162_rn(v.x, v.y);
        __nv_bfloat162 h1 = __floats2bfloat162_rn(v.z, v.w);
        ((uint2*)g_kh)[i] = make_uint2(*(uint32_t*)&h0, *(uint32_t*)&h1);
    }
}

// ---------------- key tile loader: 64 keys x 256B, XOR-swizzled ------------
__device__ __forceinline__ void load_ktile(uint32_t stage_u, int key0, bool valid, int tid) {
    if (valid) {
        #pragma unroll
        for (int c = tid; c < 1024; c += 256) {
            int row = c >> 4, ch = c & 15;
            uint32_t off = (uint32_t)(row * 256 + (((ch ^ (row & 7))) << 4));
            cp16(stage_u + off, g_kh + (size_t)(key0 + row) * DIM + ch * 8);
        }
    }
    CP_COMMIT();
}

// ---------------- main filter kernel: 256 threads, 2 CTAs/SM ---------------
__global__ void __launch_bounds__(256, 2)
sim_topk(int N, int Ntiles) {
    extern __shared__ __align__(16) char sm[];
    uint32_t smb = smem_u32(sm);
    uint32_t stage_u = (smb + 1023u) & ~1023u;

    int tid = threadIdx.x;
    int wid = tid >> 5;
    int lane = tid & 31;
    int wq = wid & 3;            // query-row group (32 rows)
    int kq = wid >> 2;           // key half (32 of the 64 tile keys)
    int qbase = blockIdx.x * 128;
    int slice = blockIdx.y;

    int TPC = (Ntiles + NSLICE - 1) / NSLICE;     // 87 (< 128, fits 7 bits)
    int t0 = slice * TPC;
    int T = min(TPC, Ntiles - t0); if (T < 0) T = 0;

    load_ktile(stage_u,         (t0 + 0) * 64, 0 < T, tid);
    load_ktile(stage_u + 16384, (t0 + 1) * 64, 1 < T, tid);

    // preload A fragments: this warp's 32 query rows = 2 m16 blocks
    int qr = qbase + wq * 32 + (lane >> 2);
    uint32_t ah[8][8];           // [kc][m*4 + j]
    #pragma unroll
    for (int kc = 0; kc < 8; ++kc) {
        int c = kc * 16 + (lane & 3) * 2;
        #pragma unroll
        for (int m = 0; m < 2; ++m) {
            const __nv_bfloat16* qp = g_qh + (size_t)(qr + m * 16) * DIM;
            ah[kc][m * 4 + 0] = *(const uint32_t*)(qp + c);
            ah[kc][m * 4 + 1] = *(const uint32_t*)(qp + 8 * DIM + c);
            ah[kc][m * 4 + 2] = *(const uint32_t*)(qp + c + 8);
            ah[kc][m * 4 + 3] = *(const uint32_t*)(qp + 8 * DIM + c + 8);
        }
    }

    // 4 per-lane top-3 QUAD lists (rows +0,+8,+16,+24), meta in low 8 bits
    float lv[4][3];
    #pragma unroll
    for (int l = 0; l < 4; ++l)
        lv[l][0] = lv[l][1] = lv[l][2] = -3.0e38f;

    int r_   = lane & 7;
    int cbit = (lane >> 3) & 1;
    int kb256 = (kq << 13) + ((lane >> 4) * 8 + r_) * 256;

    // precompute swizzled LDSM offsets (constant across tiles)
    uint32_t off_h[8];
    #pragma unroll
    for (int kc = 0; kc < 8; ++kc)
        off_h[kc] = (uint32_t)kb256 + (uint32_t)(((kc * 2 + cbit) ^ r_) << 4);

    uint32_t stA = stage_u, stB = stage_u + 16384, stC = stage_u + 32768;
    const float fzero = 0.0f;

    for (int t = 0; t < T; ++t) {
        CP_WAIT(1);
        __syncthreads();

        load_ktile(stC, (t0 + t + 2) * 64, (t + 2) < T, tid);

        #pragma unroll
        for (int nbp = 0; nbp < 2; ++nbp) {
            float acc[2][2][4];              // [m][n][j]
            #pragma unroll
            for (int kc = 0; kc < 8; ++kc) {
                uint32_t bh0, bh1, bh2, bh3;
                LDSM4(bh0, bh1, bh2, bh3, stA + off_h[kc] + nbp * 4096);
                if (kc == 0) {
                    MMA16816_Z(acc[0][0], (&ah[kc][0]), bh0, bh1, fzero);
                    MMA16816_Z(acc[0][1], (&ah[kc][0]), bh2, bh3, fzero);
                    MMA16816_Z(acc[1][0], (&ah[kc][4]), bh0, bh1, fzero);
                    MMA16816_Z(acc[1][1], (&ah[kc][4]), bh2, bh3, fzero);
                } else {
                    MMA16816(acc[0][0], (&ah[kc][0]), bh0, bh1);
                    MMA16816(acc[0][1], (&ah[kc][0]), bh2, bh3);
                    MMA16816(acc[1][0], (&ah[kc][4]), bh0, bh1);
                    MMA16816(acc[1][1], (&ah[kc][4]), bh2, bh3);
                }
            }

            // ---- quad-max scan: 1 candidate per row per nbp
            // quad = keys {p, p+1, p+8, p+9}; members recovered by exact rescore
            uint32_t meta = ((uint32_t)t << 1) | (uint32_t)nbp;   // 8 bits
            #pragma unroll
            for (int m = 0; m < 2; ++m) {
                float qlo = fmaxf(fmaxf(acc[m][0][0], acc[m][0][1]),
                                  fmaxf(acc[m][1][0], acc[m][1][1]));
                uint32_t s = (__float_as_uint(qlo) & 0xFFFFFF00u) | meta;
                ins3(lv[m * 2][0], lv[m * 2][1], lv[m * 2][2], __uint_as_float(s));
                float qhi = fmaxf(fmaxf(acc[m][0][2], acc[m][0][3]),
                                  fmaxf(acc[m][1][2], acc[m][1][3]));
                s = (__float_as_uint(qhi) & 0xFFFFFF00u) | meta;
                ins3(lv[m * 2 + 1][0], lv[m * 2 + 1][1], lv[m * 2 + 1][2],
                     __uint_as_float(s));
            }
        }

        uint32_t tmp = stA; stA = stB; stB = stC; stC = tmp;
    }

    CP_WAIT(0);

    // ---- decode packed quad candidates, merge across the 4 lanes per row ---
    int cb = kq * 32 + (lane & 3) * 2;   // key base within 64-key tile
    #pragma unroll
    for (int l = 0; l < 4; ++l) {
        float tv[K8]; int ti[K8];
        #pragma unroll
        for (int r = 0; r < 3; ++r) {
            uint32_t u = __float_as_uint(lv[l][r]);
            tv[r] = lv[l][r];
            // quad BASE index: members are base + {0, 1, 8, 9}
            ti[r] = (t0 + (int)((u >> 1) & 0x7F)) * 64 + cb + (int)(u & 1) * 16;
        }
        #pragma unroll
        for (int r = 3; r < K8; ++r) { tv[r] = -INFINITY; ti[r] = -1; }

        t8_merge_xor(tv, ti, 1);
        t8_merge_xor(tv, ti, 2);

        if ((lane & 3) == 0) {
            int row = wq * 32 + (lane >> 2) + l * 8;
            size_t slotbase = (size_t)((blockIdx.x * NSLICE + slice) * 2 + kq) * 128;
            size_t b = (slotbase + row) * PK;
            #pragma unroll
            for (int r = 0; r < PK; ++r) { g_pval[b + r] = tv[r]; g_pidx[b + r] = ti[r]; }
        }
    }
}

// ---------------- merge + exact member rescore + softmax/gather/normalize ---
__global__ void merge_out(const float* __restrict__ mem, float* __restrict__ out,
                          int N, int B) {
    int q = (blockIdx.x * blockDim.x + threadIdx.x) >> 5;
    int lane = threadIdx.x & 31;
    if (q >= B) return;
    int qtile = q >> 7, ql = q & 127;
    int exq = g_excl[q];

    // ---- phase 1: approx top-RESC quads of 288 candidates (9 per lane).
    // Filter only garbage ids (>= N); exq handled per-member in rescore.
    float cv[9]; int ci[9];
    #pragma unroll
    for (int s = 0; s < 9; ++s) {
        int cidx = lane + 32 * s;                       // < 288 always
        int c = cidx >> 2, r = cidx & 3;
        size_t base = ((size_t)(qtile * NSLOTS + c) * 128 + ql) * PK + r;
        float v = g_pval[base]; int id = g_pidx[base];
        if ((unsigned)id >= (unsigned)N) v = -INFINITY;
        cv[s] = v; ci[s] = id;
    }

    int ridx[RESC];
    #pragma unroll
    for (int k = 0; k < RESC; ++k) {
        float bv = cv[0]; int bi = ci[0];
        #pragma unroll
        for (int s = 1; s < 9; ++s)
            if (cv[s] > bv || (cv[s] == bv && ci[s] < bi)) { bv = cv[s]; bi = ci[s]; }
        #pragma unroll
        for (int o = 16; o; o >>= 1) {
            float ov = __shfl_xor_sync(0xffffffffu, bv, o);
            int   oi = __shfl_xor_sync(0xffffffffu, bi, o);
            if (ov > bv || (ov == bv && oi < bi)) { bv = ov; bi = oi; }
        }
        ridx[k] = (bi < 0 || bi >= N) ? 0 : bi;   // safety clamp (quad base)
        #pragma unroll
        for (int s = 0; s < 9; ++s) if (ci[s] == bi) cv[s] = -INFINITY;
    }

    // ---- phase 2: exact fp32 rescore of ALL 4 members of each quad
    float4 qv = *(const float4*)(g_qn + (size_t)q * DIM + lane * 4);
    float rv[4 * RESC];
    #pragma unroll
    for (int k = 0; k < RESC; ++k) {
        #pragma unroll
        for (int mb = 0; mb < 4; ++mb) {
            int id = ridx[k] + (mb & 1) + ((mb >> 1) << 3);   // +{0,1,8,9}
            float4 m4 = *(const float4*)(mem + (size_t)id * DIM + lane * 4);
            float d = qv.x * m4.x + qv.y * m4.y + qv.z * m4.z + qv.w * m4.w;
            #pragma unroll
            for (int o = 16; o; o >>= 1) d += __shfl_xor_sync(0xffffffffu, d, o);
            rv[k * 4 + mb] = (id < N && id != exq) ? d : -INFINITY;
        }
    }

    // ---- phase 3: exact top-5 over 40 members (lower index wins ties)
    float tv[TOPK]; int ti[TOPK];
    unsigned long long usedmask = 0ULL;
    #pragma unroll
    for (int k = 0; k < TOPK; ++k) {
        float bv = -INFINITY; int bi = 0x7fffffff, bs = -1;
        #pragma unroll
        for (int j = 0; j < 4 * RESC; ++j) {
            int id = ridx[j >> 2] + (j & 1) + ((j >> 1) & 1) * 8;
            if (!((usedmask >> j) & 1ULL) &&
                (rv[j] > bv || (rv[j] == bv && id < bi))) {
                bv = rv[j]; bi = id; bs = j;
            }
        }
        usedmask |= 1ULL << bs;
        tv[k] = bv; ti[k] = bi;
    }

    // ---- softmax over exact top sims
    float e[TOPK], ssum = 0.f;
    #pragma unroll
    for (int k = 0; k < TOPK; ++k) { e[k] = expf((tv[k] - tv[0]) * INV_T); ssum += e[k]; }
    float w[TOPK];
    #pragma unroll
    for (int k = 0; k < TOPK; ++k) w[k] = e[k] / ssum;

    // ---- weighted gather + renormalize
    int d0 = lane * 4;
    float4 a = make_float4(0.f, 0.f, 0.f, 0.f);
    #pragma unroll
    for (int k = 0; k < TOPK; ++k) {
        float4 m4 = *(const float4*)(mem + (size_t)ti[k] * DIM + d0);
        a.x += w[k] * m4.x; a.y += w[k] * m4.y; a.z += w[k] * m4.z; a.w += w[k] * m4.w;
    }
    float ss = a.x * a.x + a.y * a.y + a.z * a.z + a.w * a.w;
    #pragma unroll
    for (int o = 16; o; o >>= 1) ss += __shfl_xor_sync(0xffffffffu, ss, o);
    float sc = 1.0f / fmaxf(sqrtf(ss), 1e-12f);
    float4 r4 = make_float4(a.x * sc, a.y * sc, a.z * sc, a.w * sc);
    *(float4*)(out + (size_t)q * DIM + d0) = r4;

    if (lane == 0) {
        out[(size_t)B * DIM + q] = 1.0f - tv[0];
        #pragma unroll
        for (int k = 0; k < TOPK; ++k)
            out[(size_t)B * DIM + B + (size_t)q * TOPK + k] = w[k];
    }
}

// ---------------- launch ----------------
extern "C" void kernel_launch(void* const* d_in, const int* in_sizes, int n_in,
                              void* d_out, int out_size) {
    const float* query  = (const float*)d_in[0];
    const float* memory = (const float*)d_in[1];
    const void*  excl   = d_in[3];
    int B = in_sizes[0] / DIM;              // 1024
    int N = in_sizes[1] / DIM;              // 200000
    int Ntiles = (N + 63) / 64;             // 3125 tiles of 64 keys
    int NPAD = Ntiles * 64;
    float* out = (float*)d_out;

    prep_all<<<B / 8 + 1, 256>>>(query, excl, B);
    split_mem<<<2048, 256>>>(memory, N, NPAD);

    const int SMEM = 3 * 16384 + 1024;      // 50,176 B per CTA (2 CTAs/SM)
    cudaFuncSetAttribute(sim_topk, cudaFuncAttributeMaxDynamicSharedMemorySize, SMEM);
    sim_topk<<<dim3(B / 128, NSLICE), 256, SMEM>>>(N, Ntiles);

    merge_out<<<(B * 32 + 255) / 256, 256>>>(memory, out, N, B);
}

// round 14
// speedup vs baseline: 1.2001x; 1.0358x over previous
#include <cuda_runtime.h>
#include <cuda_bf16.h>
#include <math.h>
#include <stdint.h>

// ---------------- problem constants ----------------
#define MAXB     1024
#define DIM      128
#define NSLICE   36                 // key slices (grid.y)
#define NSLOTS   (NSLICE * 2)       // per-slice key-halves
#define PK       4                  // stored candidate depth per slot
#define K8       8                  // merge list depth
#define TOPK     5
#define RESC     10                 // rescored quad candidates per query
#define INV_T    10.0f
#define NPADMAX  (3128 * 64)

// ---------------- device scratch ----------------
__device__ int   g_excl[MAXB];
__device__ float g_qn[MAXB * DIM];                       // normalized queries fp32
__device__ float g_pval[8 * NSLOTS * 128 * PK];
__device__ int   g_pidx[8 * NSLOTS * 128 * PK];
__device__ __nv_bfloat16 g_qh[MAXB * DIM];
__device__ __nv_bfloat16 g_kh[(size_t)NPADMAX * DIM];    // 51.2 MB

// ---------------- PTX helpers ----------------
__device__ __forceinline__ uint32_t smem_u32(const void* p) {
    uint32_t a;
    asm("{ .reg .u64 t; cvta.to.shared.u64 t, %1; cvt.u32.u64 %0, t; }" : "=r"(a) : "l"(p));
    return a;
}
__device__ __forceinline__ void cp16(uint32_t s, const void* g) {
    asm volatile("cp.async.cg.shared.global [%0], [%1], 16;" :: "r"(s), "l"(g));
}
#define CP_COMMIT()  asm volatile("cp.async.commit_group;")
#define CP_WAIT(n)   asm volatile("cp.async.wait_group %0;" :: "n"(n))

#define LDSM4(r0, r1, r2, r3, addr)                                         \
    asm volatile("ldmatrix.sync.aligned.m8n8.x4.shared.b16 {%0,%1,%2,%3}, [%4];" \
                 : "=r"(r0), "=r"(r1), "=r"(r2), "=r"(r3) : "r"(addr))

#define MMA16816(c, a, b0, b1)                                              \
    asm volatile("mma.sync.aligned.m16n8k16.row.col.f32.bf16.bf16.f32 "     \
                 "{%0,%1,%2,%3},{%4,%5,%6,%7},{%8,%9},{%0,%1,%2,%3};"       \
                 : "+f"((c)[0]), "+f"((c)[1]), "+f"((c)[2]), "+f"((c)[3])   \
                 : "r"((a)[0]), "r"((a)[1]), "r"((a)[2]), "r"((a)[3]),      \
                   "r"(b0), "r"(b1))

// first-k MMA: D = A*B + 0 (separate zero C input; kills acc-init MOVs)
#define MMA16816_Z(c, a, b0, b1, zr)                                        \
    asm volatile("mma.sync.aligned.m16n8k16.row.col.f32.bf16.bf16.f32 "     \
                 "{%0,%1,%2,%3},{%4,%5,%6,%7},{%8,%9},{%10,%10,%10,%10};"   \
                 : "=f"((c)[0]), "=f"((c)[1]), "=f"((c)[2]), "=f"((c)[3])   \
                 : "r"((a)[0]), "r"((a)[1]), "r"((a)[2]), "r"((a)[3]),      \
                   "r"(b0), "r"(b1), "f"(zr))

// ---------------- branchless sorted-3 insert (5 FMNMX, no indices) --------
__device__ __forceinline__ void ins3(float &a, float &b, float &c, float x) {
    float m;
    m = fmaxf(a, x); x = fminf(a, x); a = m;
    m = fmaxf(b, x); x = fminf(b, x); b = m;
    c = fmaxf(c, x);
}

// ---------------- top-8 (value,idx) helpers for the endgame merge ----------
__device__ __forceinline__ void t8_ins(float (&tv)[K8], int (&ti)[K8], float s, int idx) {
    tv[K8 - 1] = s; ti[K8 - 1] = idx;
    #pragma unroll
    for (int p = K8 - 1; p > 0; --p) {
        if (tv[p] > tv[p - 1]) {
            float fv = tv[p]; tv[p] = tv[p - 1]; tv[p - 1] = fv;
            int fi = ti[p]; ti[p] = ti[p - 1]; ti[p - 1] = fi;
        }
    }
}
__device__ __forceinline__ void t8_merge_xor(float (&tv)[K8], int (&ti)[K8], int off) {
    float pv[K8]; int pi[K8];
    #pragma unroll
    for (int r = 0; r < K8; ++r) {
        pv[r] = __shfl_xor_sync(0xffffffffu, tv[r], off);
        pi[r] = __shfl_xor_sync(0xffffffffu, ti[r], off);
    }
    #pragma unroll
    for (int r = 0; r < K8; ++r)
        if (pv[r] > tv[K8 - 1]) t8_ins(tv, ti, pv[r], pi[r]);
}

// ---------------- kernel: fused query prep + exclude decode ----------------
__global__ void prep_all(const float* __restrict__ q, const void* __restrict__ ex,
                         int B) {
    if (blockIdx.x < (unsigned)(B / 8)) {
        int w = blockIdx.x * 8 + (threadIdx.x >> 5);
        int lane = threadIdx.x & 31;
        float4 v = *(const float4*)(q + (size_t)w * DIM + lane * 4);
        float ss = v.x * v.x + v.y * v.y + v.z * v.z + v.w * v.w;
        #pragma unroll
        for (int o = 16; o; o >>= 1) ss += __shfl_xor_sync(0xffffffffu, ss, o);
        float sc = 1.0f / fmaxf(sqrtf(ss), 1e-12f);
        float4 r = make_float4(v.x * sc, v.y * sc, v.z * sc, v.w * sc);
        size_t off = (size_t)w * DIM + lane * 4;
        *(float4*)(g_qn + off) = r;
        __nv_bfloat162 h0 = __floats2bfloat162_rn(r.x, r.y);
        __nv_bfloat162 h1 = __floats2bfloat162_rn(r.z, r.w);
        *(uint2*)(g_qh + off) = make_uint2(*(uint32_t*)&h0, *(uint32_t*)&h1);
    } else {
        // exclude decode: int32 vs int64 sniff
        __shared__ int nz;
        int t = threadIdx.x;
        if (t == 0) nz = 0;
        __syncthreads();
        const int* e32 = (const int*)ex;
        for (int i = t; i < B / 2; i += blockDim.x)
            if (e32[2 * i + 1] != 0) atomicAdd(&nz, 1);
        __syncthreads();
        bool is64 = (nz == 0);
        for (int i = t; i < B; i += blockDim.x) {
            long long v = is64 ? ((const long long*)ex)[i] : (long long)e32[i];
            g_excl[i] = (int)v;
        }
    }
}

// ---------------- kernel: fp32 memory -> bf16 hi ----------------
__global__ void split_mem(const float* __restrict__ mem, int N, int NPAD) {
    int total4 = NPAD * (DIM / 4);
    for (int i = blockIdx.x * blockDim.x + threadIdx.x; i < total4;
         i += gridDim.x * blockDim.x) {
        int row = i >> 5;
        float4 v = make_float4(0.f, 0.f, 0.f, 0.f);
        if (row < N) v = ((const float4*)mem)[i];
        __nv_bfloat162 h0 = __floats2bfloat162_rn(v.x, v.y);
        __nv_bfloat162 h1 = __floats2bfloat162_rn(v.z, v.w);
        ((uint2*)g_kh)[i] = make_uint2(*(uint32_t*)&h0, *(uint32_t*)&h1);
    }
}

// ---------------- key tile loader: 64 keys x 256B, XOR-swizzled ------------
__device__ __forceinline__ void load_ktile(uint32_t stage_u, int key0, bool valid, int tid) {
    if (valid) {
        #pragma unroll
        for (int c = tid; c < 1024; c += 256) {
            int row = c >> 4, ch = c & 15;
            uint32_t off = (uint32_t)(row * 256 + (((ch ^ (row & 7))) << 4));
            cp16(stage_u + off, g_kh + (size_t)(key0 + row) * DIM + ch * 8);
        }
    }
    CP_COMMIT();
}

// ---------------- main filter kernel: 256 threads, 2 CTAs/SM ---------------
__global__ void __launch_bounds__(256, 2)
sim_topk(int N, int Ntiles) {
    extern __shared__ __align__(16) char sm[];
    uint32_t smb = smem_u32(sm);
    uint32_t stage_u = (smb + 1023u) & ~1023u;

    int tid = threadIdx.x;
    int wid = tid >> 5;
    int lane = tid & 31;
    int wq = wid & 3;            // query-row group (32 rows)
    int kq = wid >> 2;           // key half (32 of the 64 tile keys)
    int qbase = blockIdx.x * 128;
    int slice = blockIdx.y;

    int TPC = (Ntiles + NSLICE - 1) / NSLICE;     // 87 (< 128, fits 7 bits)
    int t0 = slice * TPC;
    int T = min(TPC, Ntiles - t0); if (T < 0) T = 0;

    // prologue: 4 tiles in flight (6 stages total)
    load_ktile(stage_u,             (t0 + 0) * 64, 0 < T, tid);
    load_ktile(stage_u + 16384,     (t0 + 1) * 64, 1 < T, tid);
    load_ktile(stage_u + 2 * 16384, (t0 + 2) * 64, 2 < T, tid);
    load_ktile(stage_u + 3 * 16384, (t0 + 3) * 64, 3 < T, tid);

    // preload A fragments: this warp's 32 query rows = 2 m16 blocks
    int qr = qbase + wq * 32 + (lane >> 2);
    uint32_t ah[8][8];           // [kc][m*4 + j]
    #pragma unroll
    for (int kc = 0; kc < 8; ++kc) {
        int c = kc * 16 + (lane & 3) * 2;
        #pragma unroll
        for (int m = 0; m < 2; ++m) {
            const __nv_bfloat16* qp = g_qh + (size_t)(qr + m * 16) * DIM;
            ah[kc][m * 4 + 0] = *(const uint32_t*)(qp + c);
            ah[kc][m * 4 + 1] = *(const uint32_t*)(qp + 8 * DIM + c);
            ah[kc][m * 4 + 2] = *(const uint32_t*)(qp + c + 8);
            ah[kc][m * 4 + 3] = *(const uint32_t*)(qp + 8 * DIM + c + 8);
        }
    }

    // 4 per-lane top-3 QUAD lists (rows +0,+8,+16,+24), meta in low 8 bits
    float lv[4][3];
    #pragma unroll
    for (int l = 0; l < 4; ++l)
        lv[l][0] = lv[l][1] = lv[l][2] = -3.0e38f;

    int r_   = lane & 7;
    int cbit = (lane >> 3) & 1;
    int kb256 = (kq << 13) + ((lane >> 4) * 8 + r_) * 256;

    // precompute swizzled LDSM offsets (constant across tiles)
    uint32_t off_h[8];
    #pragma unroll
    for (int kc = 0; kc < 8; ++kc)
        off_h[kc] = (uint32_t)kb256 + (uint32_t)(((kc * 2 + cbit) ^ r_) << 4);

    const float fzero = 0.0f;
    uint32_t st = stage_u;                        // stage of tile t (rotates by 16KB)
    uint32_t pf = stage_u + 4 * 16384;            // stage for prefetch (t+4)
    const uint32_t stage_end = stage_u + 6 * 16384;

    for (int t = 0; t < T; ++t) {
        if ((t & 1) == 0) {
            CP_WAIT(2);                            // tiles t, t+1 resident
            __syncthreads();
            // prefetch tiles t+4, t+5 into the two stages freed at t-2, t-1
            load_ktile(pf, (t0 + t + 4) * 64, (t + 4) < T, tid);
            pf += 16384; if (pf >= stage_end) pf = stage_u;
            load_ktile(pf, (t0 + t + 5) * 64, (t + 5) < T, tid);
            pf += 16384; if (pf >= stage_end) pf = stage_u;
        }

        #pragma unroll
        for (int nbp = 0; nbp < 2; ++nbp) {
            float acc[2][2][4];              // [m][n][j]
            #pragma unroll
            for (int kc = 0; kc < 8; ++kc) {
                uint32_t bh0, bh1, bh2, bh3;
                LDSM4(bh0, bh1, bh2, bh3, st + off_h[kc] + nbp * 4096);
                if (kc == 0) {
                    MMA16816_Z(acc[0][0], (&ah[kc][0]), bh0, bh1, fzero);
                    MMA16816_Z(acc[1][0], (&ah[kc][4]), bh0, bh1, fzero);
                    MMA16816_Z(acc[0][1], (&ah[kc][0]), bh2, bh3, fzero);
                    MMA16816_Z(acc[1][1], (&ah[kc][4]), bh2, bh3, fzero);
                } else {
                    MMA16816(acc[0][0], (&ah[kc][0]), bh0, bh1);
                    MMA16816(acc[1][0], (&ah[kc][4]), bh0, bh1);
                    MMA16816(acc[0][1], (&ah[kc][0]), bh2, bh3);
                    MMA16816(acc[1][1], (&ah[kc][4]), bh2, bh3);
                }
            }

            // ---- quad-max scan: 1 candidate per row per nbp
            // quad = keys {p, p+1, p+8, p+9}; members recovered by exact rescore
            uint32_t meta = ((uint32_t)t << 1) | (uint32_t)nbp;   // 8 bits
            #pragma unroll
            for (int m = 0; m < 2; ++m) {
                float qlo = fmaxf(fmaxf(acc[m][0][0], acc[m][0][1]),
                                  fmaxf(acc[m][1][0], acc[m][1][1]));
                uint32_t s = (__float_as_uint(qlo) & 0xFFFFFF00u) | meta;
                ins3(lv[m * 2][0], lv[m * 2][1], lv[m * 2][2], __uint_as_float(s));
                float qhi = fmaxf(fmaxf(acc[m][0][2], acc[m][0][3]),
                                  fmaxf(acc[m][1][2], acc[m][1][3]));
                s = (__float_as_uint(qhi) & 0xFFFFFF00u) | meta;
                ins3(lv[m * 2 + 1][0], lv[m * 2 + 1][1], lv[m * 2 + 1][2],
                     __uint_as_float(s));
            }
        }

        st += 16384; if (st >= stage_end) st = stage_u;
    }

    CP_WAIT(0);

    // ---- decode packed quad candidates, merge across the 4 lanes per row ---
    int cb = kq * 32 + (lane & 3) * 2;   // key base within 64-key tile
    #pragma unroll
    for (int l = 0; l < 4; ++l) {
        float tv[K8]; int ti[K8];
        #pragma unroll
        for (int r = 0; r < 3; ++r) {
            uint32_t u = __float_as_uint(lv[l][r]);
            tv[r] = lv[l][r];
            // quad BASE index: members are base + {0, 1, 8, 9}
            ti[r] = (t0 + (int)((u >> 1) & 0x7F)) * 64 + cb + (int)(u & 1) * 16;
        }
        #pragma unroll
        for (int r = 3; r < K8; ++r) { tv[r] = -INFINITY; ti[r] = -1; }

        t8_merge_xor(tv, ti, 1);
        t8_merge_xor(tv, ti, 2);

        if ((lane & 3) == 0) {
            int row = wq * 32 + (lane >> 2) + l * 8;
            size_t slotbase = (size_t)((blockIdx.x * NSLICE + slice) * 2 + kq) * 128;
            size_t b = (slotbase + row) * PK;
            #pragma unroll
            for (int r = 0; r < PK; ++r) { g_pval[b + r] = tv[r]; g_pidx[b + r] = ti[r]; }
        }
    }
}

// ---------------- merge + exact member rescore + softmax/gather/normalize ---
__global__ void merge_out(const float* __restrict__ mem, float* __restrict__ out,
                          int N, int B) {
    int q = (blockIdx.x * blockDim.x + threadIdx.x) >> 5;
    int lane = threadIdx.x & 31;
    if (q >= B) return;
    int qtile = q >> 7, ql = q & 127;
    int exq = g_excl[q];

    // ---- phase 1: approx top-RESC quads of 288 candidates (9 per lane).
    // Filter only garbage ids (>= N); exq handled per-member in rescore.
    float cv[9]; int ci[9];
    #pragma unroll
    for (int s = 0; s < 9; ++s) {
        int cidx = lane + 32 * s;                       // < 288 always
        int c = cidx >> 2, r = cidx & 3;
        size_t base = ((size_t)(qtile * NSLOTS + c) * 128 + ql) * PK + r;
        float v = g_pval[base]; int id = g_pidx[base];
        if ((unsigned)id >= (unsigned)N) v = -INFINITY;
        cv[s] = v; ci[s] = id;
    }

    int ridx[RESC];
    #pragma unroll
    for (int k = 0; k < RESC; ++k) {
        float bv = cv[0]; int bi = ci[0];
        #pragma unroll
        for (int s = 1; s < 9; ++s)
            if (cv[s] > bv || (cv[s] == bv && ci[s] < bi)) { bv = cv[s]; bi = ci[s]; }
        #pragma unroll
        for (int o = 16; o; o >>= 1) {
            float ov = __shfl_xor_sync(0xffffffffu, bv, o);
            int   oi = __shfl_xor_sync(0xffffffffu, bi, o);
            if (ov > bv || (ov == bv && oi < bi)) { bv = ov; bi = oi; }
        }
        ridx[k] = (bi < 0 || bi >= N) ? 0 : bi;   // safety clamp (quad base)
        #pragma unroll
        for (int s = 0; s < 9; ++s) if (ci[s] == bi) cv[s] = -INFINITY;
    }

    // ---- phase 2: exact fp32 rescore of ALL 4 members of each quad
    float4 qv = *(const float4*)(g_qn + (size_t)q * DIM + lane * 4);
    float rv[4 * RESC];
    #pragma unroll
    for (int k = 0; k < RESC; ++k) {
        #pragma unroll
        for (int mb = 0; mb < 4; ++mb) {
            int id = ridx[k] + (mb & 1) + ((mb >> 1) << 3);   // +{0,1,8,9}
            float4 m4 = *(const float4*)(mem + (size_t)id * DIM + lane * 4);
            float d = qv.x * m4.x + qv.y * m4.y + qv.z * m4.z + qv.w * m4.w;
            #pragma unroll
            for (int o = 16; o; o >>= 1) d += __shfl_xor_sync(0xffffffffu, d, o);
            rv[k * 4 + mb] = (id < N && id != exq) ? d : -INFINITY;
        }
    }

    // ---- phase 3: exact top-5 over 40 members (lower index wins ties)
    float tv[TOPK]; int ti[TOPK];
    unsigned long long usedmask = 0ULL;
    #pragma unroll
    for (int k = 0; k < TOPK; ++k) {
        float bv = -INFINITY; int bi = 0x7fffffff, bs = -1;
        #pragma unroll
        for (int j = 0; j < 4 * RESC; ++j) {
            int id = ridx[j >> 2] + (j & 1) + ((j >> 1) & 1) * 8;
            if (!((usedmask >> j) & 1ULL) &&
                (rv[j] > bv || (rv[j] == bv && id < bi))) {
                bv = rv[j]; bi = id; bs = j;
            }
        }
        usedmask |= 1ULL << bs;
        tv[k] = bv; ti[k] = bi;
    }

    // ---- softmax over exact top sims
    float e[TOPK], ssum = 0.f;
    #pragma unroll
    for (int k = 0; k < TOPK; ++k) { e[k] = expf((tv[k] - tv[0]) * INV_T); ssum += e[k]; }
    float w[TOPK];
    #pragma unroll
    for (int k = 0; k < TOPK; ++k) w[k] = e[k] / ssum;

    // ---- weighted gather + renormalize
    int d0 = lane * 4;
    float4 a = make_float4(0.f, 0.f, 0.f, 0.f);
    #pragma unroll
    for (int k = 0; k < TOPK; ++k) {
        float4 m4 = *(const float4*)(mem + (size_t)ti[k] * DIM + d0);
        a.x += w[k] * m4.x; a.y += w[k] * m4.y; a.z += w[k] * m4.z; a.w += w[k] * m4.w;
    }
    float ss = a.x * a.x + a.y * a.y + a.z * a.z + a.w * a.w;
    #pragma unroll
    for (int o = 16; o; o >>= 1) ss += __shfl_xor_sync(0xffffffffu, ss, o);
    float sc = 1.0f / fmaxf(sqrtf(ss), 1e-12f);
    float4 r4 = make_float4(a.x * sc, a.y * sc, a.z * sc, a.w * sc);
    *(float4*)(out + (size_t)q * DIM + d0) = r4;

    if (lane == 0) {
        out[(size_t)B * DIM + q] = 1.0f - tv[0];
        #pragma unroll
        for (int k = 0; k < TOPK; ++k)
            out[(size_t)B * DIM + B + (size_t)q * TOPK + k] = w[k];
    }
}

// ---------------- launch ----------------
extern "C" void kernel_launch(void* const* d_in, const int* in_sizes, int n_in,
                              void* d_out, int out_size) {
    const float* query  = (const float*)d_in[0];
    const float* memory = (const float*)d_in[1];
    const void*  excl   = d_in[3];
    int B = in_sizes[0] / DIM;              // 1024
    int N = in_sizes[1] / DIM;              // 200000
    int Ntiles = (N + 63) / 64;             // 3125 tiles of 64 keys
    int NPAD = Ntiles * 64;
    float* out = (float*)d_out;

    prep_all<<<B / 8 + 1, 256>>>(query, excl, B);
    split_mem<<<2048, 256>>>(memory, N, NPAD);

    const int SMEM = 6 * 16384 + 1024;      // 99,328 B per CTA (2 CTAs/SM)
    cudaFuncSetAttribute(sim_topk, cudaFuncAttributeMaxDynamicSharedMemorySize, SMEM);
    sim_topk<<<dim3(B / 128, NSLICE), 256, SMEM>>>(N, Ntiles);

    merge_out<<<(B * 32 + 255) / 256, 256>>>(memory, out, N, B);
}